// round 2
// baseline (speedup 1.0000x reference)
#include <cuda_runtime.h>
#include <cuda_bf16.h>

// Problem constants (fixed by the reference: B=4096, E=512, H=512, SEQ=128)
#define BATCH 4096
#define EDIM  512
#define HDIM  512
#define GDIM  2048   // 4*H
#define SEQL  128

// Tile config
#define BM 64     // batch rows per block
#define BH 32     // hidden cols per gate per block (=> 128 effective GEMM cols)
#define KB 32     // K chunk
#define NTHREADS 256

// Scratch (device globals — no allocation allowed)
__device__ float g_xproj[BATCH * GDIM];        // 32 MB
__device__ float g_h[2][BATCH * HDIM];         // 16 MB
__device__ float g_c[2][BATCH * HDIM];         // 16 MB

// ---------------- packed f32x2 helpers ----------------
__device__ __forceinline__ unsigned long long pack2(float x, float y) {
    unsigned long long r;
    asm("mov.b64 %0, {%1, %2};" : "=l"(r) : "f"(x), "f"(y));
    return r;
}
__device__ __forceinline__ void fma2(unsigned long long& acc, unsigned long long a, unsigned long long b) {
    asm("fma.rn.f32x2 %0, %1, %2, %0;" : "+l"(acc) : "l"(a), "l"(b));
}
__device__ __forceinline__ float2 unpack2(unsigned long long v) {
    float2 f;
    asm("mov.b64 {%0, %1}, %2;" : "=f"(f.x), "=f"(f.y) : "l"(v));
    return f;
}

__device__ __forceinline__ float sigf(float x) {
    return __fdividef(1.0f, 1.0f + __expf(-x));
}
__device__ __forceinline__ float tanhf_fast(float x) {
    // tanh(x) = 1 - 2/(e^{2x}+1); exact limits at +/-inf, ~2^-21 relative error
    return 1.0f - __fdividef(2.0f, __expf(2.0f * x) + 1.0f);
}

// ---------------- shared GEMM core ----------------
// Computes acc[r][g] (float2) = sum_k A[m0+ty*4+r][k] * W[g*512 + n0 + tx*2 + {0,1}][k]
// A: [*, 512] row-major, W: [2048, 512] row-major. K = 512.
__device__ __forceinline__ void gemm_tile(const float* __restrict__ A,
                                          const float* __restrict__ W,
                                          int m0, int n0,
                                          unsigned long long acc[4][4]) {
    __shared__ float As[BM][KB + 4];     // [64][36] — pad for conflict-free frag loads
    __shared__ float Bs[KB][128 + 2];    // [32][130] — k-major, pad keeps 8B align + banks

    const int tid = threadIdx.x;
    const int ty = tid >> 4;   // 0..15  -> 4 batch rows each
    const int tx = tid & 15;   // 0..15  -> 2 hidden cols per gate each

    for (int kc = 0; kc < 512; kc += KB) {
        // Load A tile: 64x32 floats, 2 x float4 per thread, coalesced along k
        #pragma unroll
        for (int p = 0; p < 2; ++p) {
            int q  = tid + p * NTHREADS;   // 0..511
            int m  = q >> 3;
            int kq = q & 7;
            float4 v = *(const float4*)(A + (size_t)(m0 + m) * 512 + kc + kq * 4);
            *(float4*)(&As[m][kq * 4]) = v;
        }
        // Load W tile: 128x32 floats (4 gate groups of 32 rows), 4 x float4 per thread
        #pragma unroll
        for (int p = 0; p < 4; ++p) {
            int q  = tid + p * NTHREADS;   // 0..1023
            int n  = q >> 3;               // 0..127 packed gate-col index
            int kq = q & 7;
            int g  = n >> 5;
            int c  = n & 31;
            float4 v = *(const float4*)(W + (size_t)(g * 512 + n0 + c) * 512 + kc + kq * 4);
            Bs[kq * 4 + 0][n] = v.x;
            Bs[kq * 4 + 1][n] = v.y;
            Bs[kq * 4 + 2][n] = v.z;
            Bs[kq * 4 + 3][n] = v.w;
        }
        __syncthreads();

        #pragma unroll
        for (int k = 0; k < KB; ++k) {
            unsigned long long a2[4];
            #pragma unroll
            for (int r = 0; r < 4; ++r) {
                float a = As[ty * 4 + r][k];
                a2[r] = pack2(a, a);
            }
            unsigned long long b2[4];
            #pragma unroll
            for (int g = 0; g < 4; ++g) {
                b2[g] = *(const unsigned long long*)(&Bs[k][g * 32 + tx * 2]);
            }
            #pragma unroll
            for (int r = 0; r < 4; ++r) {
                #pragma unroll
                for (int g = 0; g < 4; ++g) {
                    fma2(acc[r][g], a2[r], b2[g]);
                }
            }
        }
        __syncthreads();
    }
}

// ---------------- x-projection: x @ W_ih^T + b_ih + b_hh ----------------
__global__ void __launch_bounds__(NTHREADS)
xproj_kernel(const float* __restrict__ x,      // [4096, 512]
             const float* __restrict__ w_ih,   // [2048, 512]
             const float* __restrict__ b_ih,   // [2048]
             const float* __restrict__ b_hh,   // [2048]
             float* __restrict__ xp)           // [4096, 2048]
{
    const int m0 = blockIdx.y * BM;
    const int n0 = blockIdx.x * BH;
    unsigned long long acc[4][4];
    #pragma unroll
    for (int r = 0; r < 4; ++r)
        #pragma unroll
        for (int g = 0; g < 4; ++g) acc[r][g] = 0ull;

    gemm_tile(x, w_ih, m0, n0, acc);

    const int tid = threadIdx.x;
    const int ty = tid >> 4;
    const int tx = tid & 15;
    const int hcol = n0 + tx * 2;

    #pragma unroll
    for (int r = 0; r < 4; ++r) {
        int b = m0 + ty * 4 + r;
        #pragma unroll
        for (int g = 0; g < 4; ++g) {
            int j = g * 512 + hcol;
            float2 v = unpack2(acc[r][g]);
            v.x += b_ih[j] + b_hh[j];
            v.y += b_ih[j + 1] + b_hh[j + 1];
            *(float2*)(xp + (size_t)b * GDIM + j) = v;
        }
    }
}

// ---------------- fused LSTM step: GEMM (4 gates) + cell update ----------------
__global__ void __launch_bounds__(NTHREADS)
lstm_step_kernel(const float* __restrict__ h_in,
                 const float* __restrict__ c_in,
                 const float* __restrict__ w_hh,   // [2048, 512]
                 const float* __restrict__ xproj,  // [4096, 2048]
                 float* __restrict__ h_out,
                 float* __restrict__ c_out)
{
    const int m0 = blockIdx.y * BM;
    const int n0 = blockIdx.x * BH;
    unsigned long long acc[4][4];
    #pragma unroll
    for (int r = 0; r < 4; ++r)
        #pragma unroll
        for (int g = 0; g < 4; ++g) acc[r][g] = 0ull;

    gemm_tile(h_in, w_hh, m0, n0, acc);

    const int tid = threadIdx.x;
    const int ty = tid >> 4;
    const int tx = tid & 15;
    const int hcol = n0 + tx * 2;

    #pragma unroll
    for (int r = 0; r < 4; ++r) {
        int b = m0 + ty * 4 + r;
        const float* xp = xproj + (size_t)b * GDIM + hcol;

        float2 gi = *(const float2*)(xp + 0 * 512);
        float2 gf = *(const float2*)(xp + 1 * 512);
        float2 gg = *(const float2*)(xp + 2 * 512);
        float2 go = *(const float2*)(xp + 3 * 512);
        float2 ai = unpack2(acc[r][0]);
        float2 af = unpack2(acc[r][1]);
        float2 ag = unpack2(acc[r][2]);
        float2 ao = unpack2(acc[r][3]);
        gi.x += ai.x; gi.y += ai.y;
        gf.x += af.x; gf.y += af.y;
        gg.x += ag.x; gg.y += ag.y;
        go.x += ao.x; go.y += ao.y;

        float2 cold = *(const float2*)(c_in + (size_t)b * HDIM + hcol);

        float ix = sigf(gi.x), iy = sigf(gi.y);
        float fx = sigf(gf.x), fy = sigf(gf.y);
        float gx = tanhf_fast(gg.x), gy = tanhf_fast(gg.y);
        float ox = sigf(go.x), oy = sigf(go.y);

        float cnx = fx * cold.x + ix * gx;
        float cny = fy * cold.y + iy * gy;
        float hnx = ox * tanhf_fast(cnx);
        float hny = oy * tanhf_fast(cny);

        *(float2*)(c_out + (size_t)b * HDIM + hcol) = make_float2(cnx, cny);
        *(float2*)(h_out + (size_t)b * HDIM + hcol) = make_float2(hnx, hny);
    }
}

extern "C" void kernel_launch(void* const* d_in, const int* in_sizes, int n_in,
                              void* d_out, int out_size) {
    const float* start_emb = (const float*)d_in[0];  // [4096, 1, 512]
    const float* h0        = (const float*)d_in[1];  // [1, 4096, 512]
    const float* c0        = (const float*)d_in[2];  // [1, 4096, 512]
    const float* w_ih      = (const float*)d_in[3];  // [2048, 512]
    const float* w_hh      = (const float*)d_in[4];  // [2048, 512]
    const float* b_ih      = (const float*)d_in[5];  // [2048]
    const float* b_hh      = (const float*)d_in[6];  // [2048]
    float* out = (float*)d_out;

    float *xproj, *hbuf, *cbuf;
    cudaGetSymbolAddress((void**)&xproj, g_xproj);
    cudaGetSymbolAddress((void**)&hbuf, g_h);
    cudaGetSymbolAddress((void**)&cbuf, g_c);
    float* h[2] = { hbuf, hbuf + (size_t)BATCH * HDIM };
    float* c[2] = { cbuf, cbuf + (size_t)BATCH * HDIM };

    const size_t stateBytes = (size_t)BATCH * HDIM * sizeof(float);
    cudaMemcpyAsync(h[0], h0, stateBytes, cudaMemcpyDeviceToDevice, 0);
    cudaMemcpyAsync(c[0], c0, stateBytes, cudaMemcpyDeviceToDevice, 0);

    dim3 grid(HDIM / BH, BATCH / BM);  // (16, 64)
    xproj_kernel<<<grid, NTHREADS>>>(start_emb, w_ih, b_ih, b_hh, xproj);

    const int nh = BATCH * HDIM;
    const bool out_has_c = (out_size >= 2 * nh);

    for (int t = 0; t < SEQL; ++t) {
        float* ho;
        float* co;
        if (t == SEQL - 1) {
            ho = out;
            co = out_has_c ? (out + nh) : c[(t + 1) & 1];
        } else {
            ho = h[(t + 1) & 1];
            co = c[(t + 1) & 1];
        }
        lstm_step_kernel<<<grid, NTHREADS>>>(h[t & 1], c[t & 1], w_hh, xproj, ho, co);
    }
}

// round 3
// speedup vs baseline: 1.8614x; 1.8614x over previous
#include <cuda_runtime.h>
#include <cuda_bf16.h>
#include <cstdint>

// Problem constants (B=4096, E=512, H=512, SEQ=128)
#define BATCH 4096
#define EDIM  512
#define HDIM  512
#define GDIM  2048
#define SEQL  128
#define NH    (BATCH * HDIM)

// ---------------- device scratch (no allocation allowed) ----------------
__device__ float g_xproj[BATCH * GDIM];                 // 32 MB
__device__ float g_c[2][NH];                            // 16 MB
__device__ __nv_bfloat16 g_hhi[2][NH];                  // 8 MB
__device__ __nv_bfloat16 g_hlo[2][NH];                  // 8 MB
__device__ __nv_bfloat16 g_whi[GDIM * HDIM];            // 2 MB (packed)
__device__ __nv_bfloat16 g_wlo[GDIM * HDIM];            // 2 MB (packed)

// ---------------- math helpers ----------------
__device__ __forceinline__ float sigf(float x) {
    return __fdividef(1.0f, 1.0f + __expf(-x));
}
__device__ __forceinline__ float tanhf_fast(float x) {
    return 1.0f - __fdividef(2.0f, __expf(2.0f * x) + 1.0f);
}

// ---------------- mma / ldmatrix wrappers ----------------
__device__ __forceinline__ void ldsm4(unsigned r[4], const void* p) {
    unsigned a = (unsigned)__cvta_generic_to_shared(p);
    asm volatile("ldmatrix.sync.aligned.m8n8.x4.shared.b16 {%0,%1,%2,%3}, [%4];"
                 : "=r"(r[0]), "=r"(r[1]), "=r"(r[2]), "=r"(r[3]) : "r"(a));
}
__device__ __forceinline__ void mma16816(float d[4], const unsigned a[4],
                                         unsigned b0, unsigned b1) {
    asm volatile(
        "mma.sync.aligned.m16n8k16.row.col.f32.bf16.bf16.f32 "
        "{%0,%1,%2,%3}, {%4,%5,%6,%7}, {%8,%9}, {%0,%1,%2,%3};"
        : "+f"(d[0]), "+f"(d[1]), "+f"(d[2]), "+f"(d[3])
        : "r"(a[0]), "r"(a[1]), "r"(a[2]), "r"(a[3]), "r"(b0), "r"(b1));
}

// ---------------- prep: split W_hh into packed bf16 hi/lo ----------------
// Packed layout: Wp[nb][p][k], p = gate*32 + hc, nb = hcol block of 32.
__global__ void prep_w_kernel(const float* __restrict__ w,
                              __nv_bfloat16* __restrict__ whi,
                              __nv_bfloat16* __restrict__ wlo) {
    int t = blockIdx.x * blockDim.x + threadIdx.x;   // 2048 * 64 threads
    int row = t >> 6;
    int k8  = (t & 63) * 8;
    int g    = row >> 9;
    int hcol = row & 511;
    int nb   = hcol >> 5;
    int hc   = hcol & 31;
    int p    = g * 32 + hc;
    size_t dst = (size_t)nb * 128 * 512 + (size_t)p * 512 + k8;
    const float* src = w + (size_t)row * 512 + k8;

    __nv_bfloat16 hi[8], lo[8];
    #pragma unroll
    for (int i = 0; i < 8; ++i) {
        float v = src[i];
        __nv_bfloat16 h = __float2bfloat16(v);
        hi[i] = h;
        lo[i] = __float2bfloat16(v - __bfloat162float(h));
    }
    *(uint4*)(whi + dst) = *(const uint4*)hi;
    *(uint4*)(wlo + dst) = *(const uint4*)lo;
}

// ---------------- prep: split h0 into bf16 hi/lo ----------------
__global__ void prep_h_kernel(const float* __restrict__ h0,
                              __nv_bfloat16* __restrict__ hhi,
                              __nv_bfloat16* __restrict__ hlo) {
    int t = blockIdx.x * blockDim.x + threadIdx.x;   // NH/8 threads
    size_t base = (size_t)t * 8;
    __nv_bfloat16 hi[8], lo[8];
    #pragma unroll
    for (int i = 0; i < 8; ++i) {
        float v = h0[base + i];
        __nv_bfloat16 h = __float2bfloat16(v);
        hi[i] = h;
        lo[i] = __float2bfloat16(v - __bfloat162float(h));
    }
    *(uint4*)(hhi + base) = *(const uint4*)hi;
    *(uint4*)(hlo + base) = *(const uint4*)lo;
}

// =====================================================================
//  x-projection (one-time, fp32 SIMT — 0.8% of runtime), from R1 kernel
// =====================================================================
#define XP_BM 64
#define XP_BH 32
#define XP_KB 32
#define XP_NT 256

__device__ __forceinline__ unsigned long long pack2(float x, float y) {
    unsigned long long r;
    asm("mov.b64 %0, {%1, %2};" : "=l"(r) : "f"(x), "f"(y));
    return r;
}
__device__ __forceinline__ void fma2(unsigned long long& acc, unsigned long long a, unsigned long long b) {
    asm("fma.rn.f32x2 %0, %1, %2, %0;" : "+l"(acc) : "l"(a), "l"(b));
}
__device__ __forceinline__ float2 unpack2(unsigned long long v) {
    float2 f;
    asm("mov.b64 {%0, %1}, %2;" : "=f"(f.x), "=f"(f.y) : "l"(v));
    return f;
}

__global__ void __launch_bounds__(XP_NT)
xproj_kernel(const float* __restrict__ x,
             const float* __restrict__ w_ih,
             const float* __restrict__ b_ih,
             const float* __restrict__ b_hh,
             float* __restrict__ xp) {
    __shared__ float As[XP_BM][XP_KB + 4];
    __shared__ float Bs[XP_KB][128 + 2];

    const int m0 = blockIdx.y * XP_BM;
    const int n0 = blockIdx.x * XP_BH;
    const int tid = threadIdx.x;
    const int ty = tid >> 4;
    const int tx = tid & 15;

    unsigned long long acc[4][4];
    #pragma unroll
    for (int r = 0; r < 4; ++r)
        #pragma unroll
        for (int g = 0; g < 4; ++g) acc[r][g] = 0ull;

    for (int kc = 0; kc < 512; kc += XP_KB) {
        #pragma unroll
        for (int p = 0; p < 2; ++p) {
            int q = tid + p * XP_NT;
            int m = q >> 3;
            int kq = q & 7;
            float4 v = *(const float4*)(x + (size_t)(m0 + m) * 512 + kc + kq * 4);
            *(float4*)(&As[m][kq * 4]) = v;
        }
        #pragma unroll
        for (int p = 0; p < 4; ++p) {
            int q = tid + p * XP_NT;
            int n = q >> 3;
            int kq = q & 7;
            int g = n >> 5;
            int c = n & 31;
            float4 v = *(const float4*)(w_ih + (size_t)(g * 512 + n0 + c) * 512 + kc + kq * 4);
            Bs[kq * 4 + 0][n] = v.x;
            Bs[kq * 4 + 1][n] = v.y;
            Bs[kq * 4 + 2][n] = v.z;
            Bs[kq * 4 + 3][n] = v.w;
        }
        __syncthreads();
        #pragma unroll
        for (int k = 0; k < XP_KB; ++k) {
            unsigned long long a2[4], b2[4];
            #pragma unroll
            for (int r = 0; r < 4; ++r) {
                float a = As[ty * 4 + r][k];
                a2[r] = pack2(a, a);
            }
            #pragma unroll
            for (int g = 0; g < 4; ++g)
                b2[g] = *(const unsigned long long*)(&Bs[k][g * 32 + tx * 2]);
            #pragma unroll
            for (int r = 0; r < 4; ++r)
                #pragma unroll
                for (int g = 0; g < 4; ++g) fma2(acc[r][g], a2[r], b2[g]);
        }
        __syncthreads();
    }

    const int hcol = n0 + tx * 2;
    #pragma unroll
    for (int r = 0; r < 4; ++r) {
        int b = m0 + ty * 4 + r;
        #pragma unroll
        for (int g = 0; g < 4; ++g) {
            int j = g * 512 + hcol;
            float2 v = unpack2(acc[r][g]);
            v.x += b_ih[j] + b_hh[j];
            v.y += b_ih[j + 1] + b_hh[j + 1];
            *(float2*)(xp + (size_t)b * GDIM + j) = v;
        }
    }
}

// =====================================================================
//  LSTM step: bf16-split tensor-core GEMM + fused cell update
//  Block tile: 128 rows x 32 hidden cols (=128 packed gate cols), K=512.
//  8 warps: warp = 32m x 16hc; warp n-tiles span all 4 gates so the
//  epilogue is thread-local (each thread owns all 4 gates per element).
// =====================================================================
__global__ void __launch_bounds__(256, 1)
lstm_step_mma(const __nv_bfloat16* __restrict__ hhi,
              const __nv_bfloat16* __restrict__ hlo,
              const float* __restrict__ c_in,
              const __nv_bfloat16* __restrict__ whi_p,
              const __nv_bfloat16* __restrict__ wlo_p,
              const float* __restrict__ xproj,
              __nv_bfloat16* __restrict__ hhi_o,
              __nv_bfloat16* __restrict__ hlo_o,
              float* __restrict__ c_out,
              float* __restrict__ outh,
              float* __restrict__ outc) {
    __shared__ __align__(16) __nv_bfloat16 Ah[128][40];
    __shared__ __align__(16) __nv_bfloat16 Al[128][40];
    __shared__ __align__(16) __nv_bfloat16 Bh[128][40];
    __shared__ __align__(16) __nv_bfloat16 Bl[128][40];

    const int tid  = threadIdx.x;
    const int lane = tid & 31;
    const int w    = tid >> 5;
    const int nb   = blockIdx.x;   // hidden-col block (32 cols)
    const int mb   = blockIdx.y;   // batch block (128 rows)
    const int warp_m = (w >> 1) * 32;
    const int hsl    = (w & 1) * 16;

    float d[2][4][2][4];
    #pragma unroll
    for (int a = 0; a < 2; ++a)
        #pragma unroll
        for (int b = 0; b < 4; ++b)
            #pragma unroll
            for (int c = 0; c < 2; ++c)
                #pragma unroll
                for (int e = 0; e < 4; ++e) d[a][b][c][e] = 0.0f;

    const __nv_bfloat16* Ahg = hhi + (size_t)mb * 128 * 512;
    const __nv_bfloat16* Alg = hlo + (size_t)mb * 128 * 512;
    const __nv_bfloat16* Bhg = whi_p + (size_t)nb * 128 * 512;
    const __nv_bfloat16* Blg = wlo_p + (size_t)nb * 128 * 512;

    // staging: 512 uint4 per tile (128 rows x 32 k), 2 per thread per array
    const int r0  = tid >> 2;
    const int r1  = 64 + (tid >> 2);
    const int kq  = (tid & 3) * 8;

    uint4 sAh[2], sAl[2], sBh[2], sBl[2];

    #define LOADSTAGE(KC) do {                                             \
        int kb_ = (KC) * 32 + kq;                                          \
        sAh[0] = *(const uint4*)(Ahg + (size_t)r0 * 512 + kb_);            \
        sAh[1] = *(const uint4*)(Ahg + (size_t)r1 * 512 + kb_);            \
        sAl[0] = *(const uint4*)(Alg + (size_t)r0 * 512 + kb_);            \
        sAl[1] = *(const uint4*)(Alg + (size_t)r1 * 512 + kb_);            \
        sBh[0] = *(const uint4*)(Bhg + (size_t)r0 * 512 + kb_);            \
        sBh[1] = *(const uint4*)(Bhg + (size_t)r1 * 512 + kb_);            \
        sBl[0] = *(const uint4*)(Blg + (size_t)r0 * 512 + kb_);            \
        sBl[1] = *(const uint4*)(Blg + (size_t)r1 * 512 + kb_);            \
    } while (0)

    LOADSTAGE(0);

    const int arow = warp_m + (lane & 15);
    const int acolo = (lane >> 4) * 8;
    const int brow = hsl + ((lane >> 4) << 3) + (lane & 7);
    const int bcolo = ((lane >> 3) & 1) * 8;

    for (int kc = 0; kc < 16; ++kc) {
        *(uint4*)(&Ah[r0][kq]) = sAh[0];
        *(uint4*)(&Ah[r1][kq]) = sAh[1];
        *(uint4*)(&Al[r0][kq]) = sAl[0];
        *(uint4*)(&Al[r1][kq]) = sAl[1];
        *(uint4*)(&Bh[r0][kq]) = sBh[0];
        *(uint4*)(&Bh[r1][kq]) = sBh[1];
        *(uint4*)(&Bl[r0][kq]) = sBl[0];
        *(uint4*)(&Bl[r1][kq]) = sBl[1];
        __syncthreads();

        if (kc < 15) LOADSTAGE(kc + 1);

        #pragma unroll
        for (int kk = 0; kk < 32; kk += 16) {
            unsigned afh[2][4], afl[2][4];
            ldsm4(afh[0], &Ah[arow][kk + acolo]);
            ldsm4(afh[1], &Ah[arow + 16][kk + acolo]);
            ldsm4(afl[0], &Al[arow][kk + acolo]);
            ldsm4(afl[1], &Al[arow + 16][kk + acolo]);

            #pragma unroll
            for (int g = 0; g < 4; ++g) {
                unsigned bfh[4], bfl[4];
                ldsm4(bfh, &Bh[g * 32 + brow][kk + bcolo]);
                ldsm4(bfl, &Bl[g * 32 + brow][kk + bcolo]);
                #pragma unroll
                for (int mt = 0; mt < 2; ++mt) {
                    mma16816(d[mt][g][0], afh[mt], bfh[0], bfh[1]);
                    mma16816(d[mt][g][0], afh[mt], bfl[0], bfl[1]);
                    mma16816(d[mt][g][0], afl[mt], bfh[0], bfh[1]);
                    mma16816(d[mt][g][1], afh[mt], bfh[2], bfh[3]);
                    mma16816(d[mt][g][1], afh[mt], bfl[2], bfl[3]);
                    mma16816(d[mt][g][1], afl[mt], bfh[2], bfh[3]);
                }
            }
        }
        __syncthreads();
    }
    #undef LOADSTAGE

    // ---------- epilogue: thread-local gate fusion ----------
    const int gid = lane >> 2;
    const int tig = lane & 3;

    #pragma unroll
    for (int mt = 0; mt < 2; ++mt) {
        #pragma unroll
        for (int rh = 0; rh < 2; ++rh) {
            int m = mb * 128 + warp_m + mt * 16 + gid + rh * 8;
            #pragma unroll
            for (int j = 0; j < 2; ++j) {
                int hcol = nb * 32 + hsl + j * 8 + tig * 2;
                const float* xp = xproj + (size_t)m * GDIM + hcol;

                float2 gi = *(const float2*)(xp + 0 * 512);
                float2 gf = *(const float2*)(xp + 1 * 512);
                float2 gg = *(const float2*)(xp + 2 * 512);
                float2 go = *(const float2*)(xp + 3 * 512);

                gi.x += d[mt][0][j][rh * 2];  gi.y += d[mt][0][j][rh * 2 + 1];
                gf.x += d[mt][1][j][rh * 2];  gf.y += d[mt][1][j][rh * 2 + 1];
                gg.x += d[mt][2][j][rh * 2];  gg.y += d[mt][2][j][rh * 2 + 1];
                go.x += d[mt][3][j][rh * 2];  go.y += d[mt][3][j][rh * 2 + 1];

                float2 cv = *(const float2*)(c_in + (size_t)m * HDIM + hcol);

                float ix = sigf(gi.x), iy = sigf(gi.y);
                float fx = sigf(gf.x), fy = sigf(gf.y);
                float gx = tanhf_fast(gg.x), gy = tanhf_fast(gg.y);
                float ox = sigf(go.x), oy = sigf(go.y);

                float cnx = fx * cv.x + ix * gx;
                float cny = fy * cv.y + iy * gy;
                float hnx = ox * tanhf_fast(cnx);
                float hny = oy * tanhf_fast(cny);

                *(float2*)(c_out + (size_t)m * HDIM + hcol) = make_float2(cnx, cny);

                __nv_bfloat16 hx = __float2bfloat16(hnx);
                __nv_bfloat16 hy = __float2bfloat16(hny);
                __nv_bfloat16 lx = __float2bfloat16(hnx - __bfloat162float(hx));
                __nv_bfloat16 ly = __float2bfloat16(hny - __bfloat162float(hy));
                __nv_bfloat162 vh; vh.x = hx; vh.y = hy;
                __nv_bfloat162 vl; vl.x = lx; vl.y = ly;
                *(__nv_bfloat162*)(hhi_o + (size_t)m * HDIM + hcol) = vh;
                *(__nv_bfloat162*)(hlo_o + (size_t)m * HDIM + hcol) = vl;

                if (outh) {
                    *(float2*)(outh + (size_t)m * HDIM + hcol) = make_float2(hnx, hny);
                    if (outc)
                        *(float2*)(outc + (size_t)m * HDIM + hcol) = make_float2(cnx, cny);
                }
            }
        }
    }
}

// =====================================================================
extern "C" void kernel_launch(void* const* d_in, const int* in_sizes, int n_in,
                              void* d_out, int out_size) {
    const float* start_emb = (const float*)d_in[0];
    const float* h0        = (const float*)d_in[1];
    const float* c0        = (const float*)d_in[2];
    const float* w_ih      = (const float*)d_in[3];
    const float* w_hh      = (const float*)d_in[4];
    const float* b_ih      = (const float*)d_in[5];
    const float* b_hh      = (const float*)d_in[6];
    float* out = (float*)d_out;

    float *xproj, *cbuf;
    __nv_bfloat16 *hhib, *hlob, *whi, *wlo;
    cudaGetSymbolAddress((void**)&xproj, g_xproj);
    cudaGetSymbolAddress((void**)&cbuf,  g_c);
    cudaGetSymbolAddress((void**)&hhib,  g_hhi);
    cudaGetSymbolAddress((void**)&hlob,  g_hlo);
    cudaGetSymbolAddress((void**)&whi,   g_whi);
    cudaGetSymbolAddress((void**)&wlo,   g_wlo);

    float* c[2]             = { cbuf, cbuf + NH };
    __nv_bfloat16* hhi[2]   = { hhib, hhib + NH };
    __nv_bfloat16* hlo[2]   = { hlob, hlob + NH };

    cudaMemcpyAsync(c[0], c0, (size_t)NH * sizeof(float), cudaMemcpyDeviceToDevice, 0);

    prep_w_kernel<<<(GDIM * 64) / 256, 256>>>(w_hh, whi, wlo);
    prep_h_kernel<<<(NH / 8) / 256, 256>>>(h0, hhi[0], hlo[0]);

    dim3 grid_xp(HDIM / XP_BH, BATCH / XP_BM);
    xproj_kernel<<<grid_xp, XP_NT>>>(start_emb, w_ih, b_ih, b_hh, xproj);

    const bool out_has_c = (out_size >= 2 * NH);
    dim3 grid_step(16, 32);   // (hcol blocks, batch blocks)

    for (int t = 0; t < SEQL; ++t) {
        int cur = t & 1, nxt = (t + 1) & 1;
        float* outh = (t == SEQL - 1) ? out : nullptr;
        float* outc = (t == SEQL - 1 && out_has_c) ? (out + NH) : nullptr;
        lstm_step_mma<<<grid_step, 256>>>(hhi[cur], hlo[cur], c[cur],
                                          whi, wlo, xproj,
                                          hhi[nxt], hlo[nxt], c[nxt],
                                          outh, outc);
    }
}

// round 5
// speedup vs baseline: 2.9894x; 1.6060x over previous
#include <cuda_runtime.h>
#include <cuda_fp16.h>
#include <cstdint>

// Problem constants (B=4096, E=512, H=512, SEQ=128)
#define BATCH 4096
#define EDIM  512
#define HDIM  512
#define GDIM  2048
#define SEQL  128
#define NH    (BATCH * HDIM)

// step-kernel pipeline config
#define NSTAGE   3
#define ROWPITCH 40                    // halves per smem row (80B, 16B aligned)
#define ARR_B    (128 * ROWPITCH * 2)  // 10240 B per array
#define STAGE_B  (3 * ARR_B)           // Ah + Al + B = 30720 B
#define SMEM_STEP (NSTAGE * STAGE_B)   // 92160 B

// ---------------- device scratch (no allocation allowed) ----------------
__device__ float g_xproj[BATCH * GDIM];          // 32 MB
__device__ float g_c[2][NH];                     // 16 MB
__device__ __half g_hhi[2][NH];                  // 8 MB
__device__ __half g_hlo[2][NH];                  // 8 MB
__device__ __half g_wp[GDIM * HDIM];             // 2 MB, packed [nb=16][p=128][k=512]

// ---------------- helpers ----------------
__device__ __forceinline__ float sigf(float x) {
    return __fdividef(1.0f, 1.0f + __expf(-x));
}
__device__ __forceinline__ float tanhf_fast(float x) {
    return 1.0f - __fdividef(2.0f, __expf(2.0f * x) + 1.0f);
}
__device__ __forceinline__ void ldsm4(unsigned r[4], const void* p) {
    unsigned a = (unsigned)__cvta_generic_to_shared(p);
    asm volatile("ldmatrix.sync.aligned.m8n8.x4.shared.b16 {%0,%1,%2,%3}, [%4];"
                 : "=r"(r[0]), "=r"(r[1]), "=r"(r[2]), "=r"(r[3]) : "r"(a));
}
__device__ __forceinline__ void mma16816(float d[4], const unsigned a[4],
                                         unsigned b0, unsigned b1) {
    asm volatile(
        "mma.sync.aligned.m16n8k16.row.col.f32.f16.f16.f32 "
        "{%0,%1,%2,%3}, {%4,%5,%6,%7}, {%8,%9}, {%0,%1,%2,%3};"
        : "+f"(d[0]), "+f"(d[1]), "+f"(d[2]), "+f"(d[3])
        : "r"(a[0]), "r"(a[1]), "r"(a[2]), "r"(a[3]), "r"(b0), "r"(b1));
}
__device__ __forceinline__ void cp16(uint32_t dst, const void* src) {
    asm volatile("cp.async.cg.shared.global [%0], [%1], 16;" :: "r"(dst), "l"(src) : "memory");
}
__device__ __forceinline__ void cp_commit() {
    asm volatile("cp.async.commit_group;" ::: "memory");
}
template <int N>
__device__ __forceinline__ void cp_wait() {
    asm volatile("cp.async.wait_group %0;" :: "n"(N) : "memory");
}

// ---------------- prep: W_hh -> packed fp16 ----------------
// layout: wp[nb][p][k], p = gate*32 + hc, nb = hcol block of 32
__global__ void prep_w_kernel(const float* __restrict__ w, __half* __restrict__ wp) {
    int t = blockIdx.x * blockDim.x + threadIdx.x;   // 2048 rows x 64 chunks
    int row = t >> 6;
    int k0  = (t & 63) * 8;
    int g = row >> 9, hcol = row & 511;
    int nb = hcol >> 5, hc = hcol & 31;
    int p = g * 32 + hc;
    const float* src = w + (size_t)row * 512 + k0;
    __half v[8];
    #pragma unroll
    for (int i = 0; i < 8; ++i) v[i] = __float2half_rn(src[i]);
    *(uint4*)(wp + (size_t)nb * 128 * 512 + (size_t)p * 512 + k0) = *(const uint4*)v;
}

// ---------------- prep: h0 -> fp16 hi/lo ----------------
__global__ void prep_h_kernel(const float* __restrict__ h0,
                              __half* __restrict__ hhi, __half* __restrict__ hlo) {
    int t = blockIdx.x * blockDim.x + threadIdx.x;   // NH/8 threads
    size_t base = (size_t)t * 8;
    __half hi[8], lo[8];
    #pragma unroll
    for (int i = 0; i < 8; ++i) {
        float v = h0[base + i];
        __half h = __float2half_rn(v);
        hi[i] = h;
        lo[i] = __float2half_rn(v - __half2float(h));
    }
    *(uint4*)(hhi + base) = *(const uint4*)hi;
    *(uint4*)(hlo + base) = *(const uint4*)lo;
}

// =====================================================================
//  x-projection (one-time, fp32 SIMT)
// =====================================================================
#define XP_NT 256
__device__ __forceinline__ unsigned long long pack2(float x, float y) {
    unsigned long long r;
    asm("mov.b64 %0, {%1, %2};" : "=l"(r) : "f"(x), "f"(y));
    return r;
}
__device__ __forceinline__ void fma2(unsigned long long& acc, unsigned long long a, unsigned long long b) {
    asm("fma.rn.f32x2 %0, %1, %2, %0;" : "+l"(acc) : "l"(a), "l"(b));
}
__device__ __forceinline__ float2 unpack2(unsigned long long v) {
    float2 f;
    asm("mov.b64 {%0, %1}, %2;" : "=f"(f.x), "=f"(f.y) : "l"(v));
    return f;
}

__global__ void __launch_bounds__(XP_NT)
xproj_kernel(const float* __restrict__ x, const float* __restrict__ w_ih,
             const float* __restrict__ b_ih, const float* __restrict__ b_hh,
             float* __restrict__ xp) {
    __shared__ float As[64][36];
    __shared__ float Bs[32][130];
    const int m0 = blockIdx.y * 64, n0 = blockIdx.x * 32;
    const int tid = threadIdx.x, ty = tid >> 4, tx = tid & 15;
    unsigned long long acc[4][4];
    #pragma unroll
    for (int r = 0; r < 4; ++r)
        #pragma unroll
        for (int g = 0; g < 4; ++g) acc[r][g] = 0ull;

    for (int kc = 0; kc < 512; kc += 32) {
        #pragma unroll
        for (int p = 0; p < 2; ++p) {
            int q = tid + p * XP_NT, m = q >> 3, kq = q & 7;
            *(float4*)(&As[m][kq * 4]) = *(const float4*)(x + (size_t)(m0 + m) * 512 + kc + kq * 4);
        }
        #pragma unroll
        for (int p = 0; p < 4; ++p) {
            int q = tid + p * XP_NT, n = q >> 3, kq = q & 7;
            int g = n >> 5, c = n & 31;
            float4 v = *(const float4*)(w_ih + (size_t)(g * 512 + n0 + c) * 512 + kc + kq * 4);
            Bs[kq * 4 + 0][n] = v.x; Bs[kq * 4 + 1][n] = v.y;
            Bs[kq * 4 + 2][n] = v.z; Bs[kq * 4 + 3][n] = v.w;
        }
        __syncthreads();
        #pragma unroll
        for (int k = 0; k < 32; ++k) {
            unsigned long long a2[4], b2[4];
            #pragma unroll
            for (int r = 0; r < 4; ++r) { float a = As[ty * 4 + r][k]; a2[r] = pack2(a, a); }
            #pragma unroll
            for (int g = 0; g < 4; ++g)
                b2[g] = *(const unsigned long long*)(&Bs[k][g * 32 + tx * 2]);
            #pragma unroll
            for (int r = 0; r < 4; ++r)
                #pragma unroll
                for (int g = 0; g < 4; ++g) fma2(acc[r][g], a2[r], b2[g]);
        }
        __syncthreads();
    }
    const int hcol = n0 + tx * 2;
    #pragma unroll
    for (int r = 0; r < 4; ++r) {
        int b = m0 + ty * 4 + r;
        #pragma unroll
        for (int g = 0; g < 4; ++g) {
            int j = g * 512 + hcol;
            float2 v = unpack2(acc[r][g]);
            v.x += b_ih[j] + b_hh[j];
            v.y += b_ih[j + 1] + b_hh[j + 1];
            *(float2*)(xp + (size_t)b * GDIM + j) = v;
        }
    }
}

// =====================================================================
//  LSTM step: fp16-split HMMA GEMM (2 MMAs/pair) + cp.async pipeline
//  Block: 128 batch rows x 32 hcols x 4 gates; 8 warps (32m x 16hc);
//  2 CTAs/SM.
// =====================================================================
__global__ void __launch_bounds__(256, 2)
lstm_step_mma(const __half* __restrict__ hhi,
              const __half* __restrict__ hlo,
              const float* __restrict__ c_in,
              const __half* __restrict__ wpk,
              const float* __restrict__ xproj,
              __half* __restrict__ hhi_o,
              __half* __restrict__ hlo_o,
              float* __restrict__ c_out,
              float* __restrict__ outh,
              float* __restrict__ outc) {
    extern __shared__ __align__(16) unsigned char smc[];
    const uint32_t sb = (uint32_t)__cvta_generic_to_shared(smc);

    const int tid  = threadIdx.x;
    const int lane = tid & 31;
    const int w    = tid >> 5;
    const int nb   = blockIdx.x;   // 32 hcols
    const int mb   = blockIdx.y;   // 128 batch rows
    const int warp_m = (w >> 1) * 32;
    const int hsl    = (w & 1) * 16;

    float d[2][4][2][4];
    #pragma unroll
    for (int a = 0; a < 2; ++a)
        #pragma unroll
        for (int b = 0; b < 4; ++b)
            #pragma unroll
            for (int c = 0; c < 2; ++c)
                #pragma unroll
                for (int e = 0; e < 4; ++e) d[a][b][c][e] = 0.0f;

    const __half* Ahg = hhi + (size_t)mb * 128 * 512;
    const __half* Alg = hlo + (size_t)mb * 128 * 512;
    const __half* Bg  = wpk + (size_t)nb * 128 * 512;

    // ---- cp.async stage issue: 1536 x 16B (Ah, Al, B: 128 rows x 64B) ----
    // per thread: 6 copies. idx -> arr(0..2), row(0..127), chunk(0..3)
    #define ISSUE(KC, SLOT) do {                                               \
        uint32_t sb0_ = sb + (SLOT) * STAGE_B;                                 \
        _Pragma("unroll")                                                      \
        for (int i_ = 0; i_ < 6; ++i_) {                                       \
            int idx_ = tid + i_ * 256;                                         \
            int arr_ = idx_ >> 9;                                              \
            int rc_  = idx_ & 511;                                             \
            int row_ = rc_ >> 2;                                               \
            int ch_  = rc_ & 3;                                                \
            const __half* s_ = (arr_ == 0 ? Ahg : (arr_ == 1 ? Alg : Bg))      \
                               + (size_t)row_ * 512 + (KC) * 32 + ch_ * 8;     \
            uint32_t d_ = sb0_ + arr_ * ARR_B + row_ * 80 + ch_ * 16;          \
            cp16(d_, s_);                                                      \
        }                                                                      \
    } while (0)

    ISSUE(0, 0); cp_commit();
    ISSUE(1, 1); cp_commit();

    const int arow  = warp_m + (lane & 15);
    const int acolo = (lane >> 4) * 8;
    const int brow  = hsl + ((lane >> 4) << 3) + (lane & 7);
    const int bcolo = ((lane >> 3) & 1) * 8;

    for (int kc = 0; kc < 16; ++kc) {
        cp_wait<1>();
        __syncthreads();
        if (kc + 2 < 16) ISSUE(kc + 2, (kc + 2) % NSTAGE);
        cp_commit();

        unsigned char* stg = smc + (kc % NSTAGE) * STAGE_B;
        __half (*Ah)[ROWPITCH] = (__half(*)[ROWPITCH])(stg);
        __half (*Al)[ROWPITCH] = (__half(*)[ROWPITCH])(stg + ARR_B);
        __half (*Bs)[ROWPITCH] = (__half(*)[ROWPITCH])(stg + 2 * ARR_B);

        #pragma unroll
        for (int kk = 0; kk < 32; kk += 16) {
            unsigned afh[2][4], afl[2][4];
            ldsm4(afh[0], &Ah[arow][kk + acolo]);
            ldsm4(afh[1], &Ah[arow + 16][kk + acolo]);
            ldsm4(afl[0], &Al[arow][kk + acolo]);
            ldsm4(afl[1], &Al[arow + 16][kk + acolo]);

            #pragma unroll
            for (int g = 0; g < 4; ++g) {
                unsigned bf[4];
                ldsm4(bf, &Bs[g * 32 + brow][kk + bcolo]);
                #pragma unroll
                for (int mt = 0; mt < 2; ++mt) {
                    mma16816(d[mt][g][0], afh[mt], bf[0], bf[1]);
                    mma16816(d[mt][g][0], afl[mt], bf[0], bf[1]);
                    mma16816(d[mt][g][1], afh[mt], bf[2], bf[3]);
                    mma16816(d[mt][g][1], afl[mt], bf[2], bf[3]);
                }
            }
        }
    }
    #undef ISSUE

    // ---------- epilogue: thread-local gate fusion ----------
    const int gid = lane >> 2;
    const int tig = lane & 3;

    #pragma unroll
    for (int mt = 0; mt < 2; ++mt) {
        #pragma unroll
        for (int rh = 0; rh < 2; ++rh) {
            int m = mb * 128 + warp_m + mt * 16 + gid + rh * 8;
            #pragma unroll
            for (int j = 0; j < 2; ++j) {
                int hcol = nb * 32 + hsl + j * 8 + tig * 2;
                const float* xp = xproj + (size_t)m * GDIM + hcol;

                float2 gi = *(const float2*)(xp + 0 * 512);
                float2 gf = *(const float2*)(xp + 1 * 512);
                float2 gg = *(const float2*)(xp + 2 * 512);
                float2 go = *(const float2*)(xp + 3 * 512);

                gi.x += d[mt][0][j][rh * 2];  gi.y += d[mt][0][j][rh * 2 + 1];
                gf.x += d[mt][1][j][rh * 2];  gf.y += d[mt][1][j][rh * 2 + 1];
                gg.x += d[mt][2][j][rh * 2];  gg.y += d[mt][2][j][rh * 2 + 1];
                go.x += d[mt][3][j][rh * 2];  go.y += d[mt][3][j][rh * 2 + 1];

                float2 cv = *(const float2*)(c_in + (size_t)m * HDIM + hcol);

                float ix = sigf(gi.x), iy = sigf(gi.y);
                float fx = sigf(gf.x), fy = sigf(gf.y);
                float gx = tanhf_fast(gg.x), gy = tanhf_fast(gg.y);
                float ox = sigf(go.x), oy = sigf(go.y);

                float cnx = fx * cv.x + ix * gx;
                float cny = fy * cv.y + iy * gy;
                float hnx = ox * tanhf_fast(cnx);
                float hny = oy * tanhf_fast(cny);

                *(float2*)(c_out + (size_t)m * HDIM + hcol) = make_float2(cnx, cny);

                __half hx = __float2half_rn(hnx);
                __half hy = __float2half_rn(hny);
                __half lx = __float2half_rn(hnx - __half2float(hx));
                __half ly = __float2half_rn(hny - __half2float(hy));
                __half2 vh; vh.x = hx; vh.y = hy;
                __half2 vl; vl.x = lx; vl.y = ly;
                *(__half2*)(hhi_o + (size_t)m * HDIM + hcol) = vh;
                *(__half2*)(hlo_o + (size_t)m * HDIM + hcol) = vl;

                if (outh) {
                    *(float2*)(outh + (size_t)m * HDIM + hcol) = make_float2(hnx, hny);
                    if (outc)
                        *(float2*)(outc + (size_t)m * HDIM + hcol) = make_float2(cnx, cny);
                }
            }
        }
    }
}

// =====================================================================
extern "C" void kernel_launch(void* const* d_in, const int* in_sizes, int n_in,
                              void* d_out, int out_size) {
    const float* start_emb = (const float*)d_in[0];
    const float* h0        = (const float*)d_in[1];
    const float* c0        = (const float*)d_in[2];
    const float* w_ih      = (const float*)d_in[3];
    const float* w_hh      = (const float*)d_in[4];
    const float* b_ih      = (const float*)d_in[5];
    const float* b_hh      = (const float*)d_in[6];
    float* out = (float*)d_out;

    float *xproj, *cbuf;
    __half *hhib, *hlob, *wp;
    cudaGetSymbolAddress((void**)&xproj, g_xproj);
    cudaGetSymbolAddress((void**)&cbuf,  g_c);
    cudaGetSymbolAddress((void**)&hhib,  g_hhi);
    cudaGetSymbolAddress((void**)&hlob,  g_hlo);
    cudaGetSymbolAddress((void**)&wp,    g_wp);

    float* c[2]       = { cbuf, cbuf + NH };
    __half* hhi[2]    = { hhib, hhib + NH };
    __half* hlo[2]    = { hlob, hlob + NH };

    cudaFuncSetAttribute(lstm_step_mma, cudaFuncAttributeMaxDynamicSharedMemorySize, SMEM_STEP);

    cudaMemcpyAsync(c[0], c0, (size_t)NH * sizeof(float), cudaMemcpyDeviceToDevice, 0);

    prep_w_kernel<<<(GDIM * 64) / 256, 256>>>(w_hh, wp);
    prep_h_kernel<<<(NH / 8) / 256, 256>>>(h0, hhi[0], hlo[0]);

    dim3 grid_xp(HDIM / 32, BATCH / 64);
    xproj_kernel<<<grid_xp, XP_NT>>>(start_emb, w_ih, b_ih, b_hh, xproj);

    const bool out_has_c = (out_size >= 2 * NH);
    dim3 grid_step(16, 32);   // (hcol blocks of 32, batch blocks of 128)

    for (int t = 0; t < SEQL; ++t) {
        int cur = t & 1, nxt = (t + 1) & 1;
        float* outh = (t == SEQL - 1) ? out : nullptr;
        float* outc = (t == SEQL - 1 && out_has_c) ? (out + NH) : nullptr;
        lstm_step_mma<<<grid_step, 256, SMEM_STEP>>>(hhi[cur], hlo[cur], c[cur],
                                                     wp, xproj,
                                                     hhi[nxt], hlo[nxt], c[nxt],
                                                     outh, outc);
    }
}

// round 6
// speedup vs baseline: 4.8566x; 1.6246x over previous
#include <cuda_runtime.h>
#include <cuda_fp16.h>
#include <cstdint>

// Problem constants (B=4096, E=512, H=512, SEQ=128)
#define BATCH 4096
#define EDIM  512
#define HDIM  512
#define GDIM  2048
#define SEQL  128
#define NH    (BATCH * HDIM)

// step-kernel pipeline config
#define NSTAGE   4
#define ROWPITCH 40                    // halves per smem row (80B, 16B aligned)
#define ARR_B    (128 * ROWPITCH * 2)  // 10240 B per array
#define STAGE_B  (2 * ARR_B)           // Ah + B = 20480 B
#define SMEM_STEP (NSTAGE * STAGE_B)   // 81920 B

// ---------------- device scratch (no allocation allowed) ----------------
__device__ float g_xproj[BATCH * GDIM];          // 32 MB
__device__ float g_c[2][NH];                     // 16 MB
__device__ __half g_h16[2][NH];                  // 8 MB
__device__ __half g_wp[GDIM * HDIM];             // 2 MB, packed [nb=16][p=128][k=512]

// ---------------- helpers ----------------
__device__ __forceinline__ float sigf(float x) {
    return __fdividef(1.0f, 1.0f + __expf(-x));
}
__device__ __forceinline__ float tanhf_fast(float x) {
    return 1.0f - __fdividef(2.0f, __expf(2.0f * x) + 1.0f);
}
__device__ __forceinline__ void ldsm4(unsigned r[4], const void* p) {
    unsigned a = (unsigned)__cvta_generic_to_shared(p);
    asm volatile("ldmatrix.sync.aligned.m8n8.x4.shared.b16 {%0,%1,%2,%3}, [%4];"
                 : "=r"(r[0]), "=r"(r[1]), "=r"(r[2]), "=r"(r[3]) : "r"(a));
}
__device__ __forceinline__ void mma16816(float d[4], const unsigned a[4],
                                         unsigned b0, unsigned b1) {
    asm volatile(
        "mma.sync.aligned.m16n8k16.row.col.f32.f16.f16.f32 "
        "{%0,%1,%2,%3}, {%4,%5,%6,%7}, {%8,%9}, {%0,%1,%2,%3};"
        : "+f"(d[0]), "+f"(d[1]), "+f"(d[2]), "+f"(d[3])
        : "r"(a[0]), "r"(a[1]), "r"(a[2]), "r"(a[3]), "r"(b0), "r"(b1));
}
__device__ __forceinline__ void cp16(uint32_t dst, const void* src) {
    asm volatile("cp.async.cg.shared.global [%0], [%1], 16;" :: "r"(dst), "l"(src) : "memory");
}
__device__ __forceinline__ void cp_commit() {
    asm volatile("cp.async.commit_group;" ::: "memory");
}
template <int N>
__device__ __forceinline__ void cp_wait() {
    asm volatile("cp.async.wait_group %0;" :: "n"(N) : "memory");
}

// ---------------- prep: W_hh -> packed fp16 ----------------
// layout: wp[nb][p][k], p = gate*32 + hc, nb = hcol block of 32
__global__ void prep_w_kernel(const float* __restrict__ w, __half* __restrict__ wp) {
    int t = blockIdx.x * blockDim.x + threadIdx.x;   // 2048 rows x 64 chunks
    int row = t >> 6;
    int k0  = (t & 63) * 8;
    int g = row >> 9, hcol = row & 511;
    int nb = hcol >> 5, hc = hcol & 31;
    int p = g * 32 + hc;
    const float* src = w + (size_t)row * 512 + k0;
    __half v[8];
    #pragma unroll
    for (int i = 0; i < 8; ++i) v[i] = __float2half_rn(src[i]);
    *(uint4*)(wp + (size_t)nb * 128 * 512 + (size_t)p * 512 + k0) = *(const uint4*)v;
}

// ---------------- prep: h0 -> fp16 ----------------
__global__ void prep_h_kernel(const float* __restrict__ h0, __half* __restrict__ h16) {
    int t = blockIdx.x * blockDim.x + threadIdx.x;   // NH/8 threads
    size_t base = (size_t)t * 8;
    __half v[8];
    #pragma unroll
    for (int i = 0; i < 8; ++i) v[i] = __float2half_rn(h0[base + i]);
    *(uint4*)(h16 + base) = *(const uint4*)v;
}

// =====================================================================
//  x-projection (one-time, fp32 SIMT)
// =====================================================================
#define XP_NT 256
__device__ __forceinline__ unsigned long long pack2(float x, float y) {
    unsigned long long r;
    asm("mov.b64 %0, {%1, %2};" : "=l"(r) : "f"(x), "f"(y));
    return r;
}
__device__ __forceinline__ void fma2(unsigned long long& acc, unsigned long long a, unsigned long long b) {
    asm("fma.rn.f32x2 %0, %1, %2, %0;" : "+l"(acc) : "l"(a), "l"(b));
}
__device__ __forceinline__ float2 unpack2(unsigned long long v) {
    float2 f;
    asm("mov.b64 {%0, %1}, %2;" : "=f"(f.x), "=f"(f.y) : "l"(v));
    return f;
}

__global__ void __launch_bounds__(XP_NT)
xproj_kernel(const float* __restrict__ x, const float* __restrict__ w_ih,
             const float* __restrict__ b_ih, const float* __restrict__ b_hh,
             float* __restrict__ xp) {
    __shared__ float As[64][36];
    __shared__ float Bs[32][130];
    const int m0 = blockIdx.y * 64, n0 = blockIdx.x * 32;
    const int tid = threadIdx.x, ty = tid >> 4, tx = tid & 15;
    unsigned long long acc[4][4];
    #pragma unroll
    for (int r = 0; r < 4; ++r)
        #pragma unroll
        for (int g = 0; g < 4; ++g) acc[r][g] = 0ull;

    for (int kc = 0; kc < 512; kc += 32) {
        #pragma unroll
        for (int p = 0; p < 2; ++p) {
            int q = tid + p * XP_NT, m = q >> 3, kq = q & 7;
            *(float4*)(&As[m][kq * 4]) = *(const float4*)(x + (size_t)(m0 + m) * 512 + kc + kq * 4);
        }
        #pragma unroll
        for (int p = 0; p < 4; ++p) {
            int q = tid + p * XP_NT, n = q >> 3, kq = q & 7;
            int g = n >> 5, c = n & 31;
            float4 v = *(const float4*)(w_ih + (size_t)(g * 512 + n0 + c) * 512 + kc + kq * 4);
            Bs[kq * 4 + 0][n] = v.x; Bs[kq * 4 + 1][n] = v.y;
            Bs[kq * 4 + 2][n] = v.z; Bs[kq * 4 + 3][n] = v.w;
        }
        __syncthreads();
        #pragma unroll
        for (int k = 0; k < 32; ++k) {
            unsigned long long a2[4], b2[4];
            #pragma unroll
            for (int r = 0; r < 4; ++r) { float a = As[ty * 4 + r][k]; a2[r] = pack2(a, a); }
            #pragma unroll
            for (int g = 0; g < 4; ++g)
                b2[g] = *(const unsigned long long*)(&Bs[k][g * 32 + tx * 2]);
            #pragma unroll
            for (int r = 0; r < 4; ++r)
                #pragma unroll
                for (int g = 0; g < 4; ++g) fma2(acc[r][g], a2[r], b2[g]);
        }
        __syncthreads();
    }
    const int hcol = n0 + tx * 2;
    #pragma unroll
    for (int r = 0; r < 4; ++r) {
        int b = m0 + ty * 4 + r;
        #pragma unroll
        for (int g = 0; g < 4; ++g) {
            int j = g * 512 + hcol;
            float2 v = unpack2(acc[r][g]);
            v.x += b_ih[j] + b_hh[j];
            v.y += b_ih[j + 1] + b_hh[j + 1];
            *(float2*)(xp + (size_t)b * GDIM + j) = v;
        }
    }
}

// =====================================================================
//  LSTM step: fp16 HMMA GEMM + cp.async 4-stage pipeline
//  Block: 128 batch rows x 32 hcols x 4 gates; 8 warps (32m x 16hc);
//  2 CTAs/SM.
// =====================================================================
__global__ void __launch_bounds__(256, 2)
lstm_step_mma(const __half* __restrict__ h_in,
              const float* __restrict__ c_in,
              const __half* __restrict__ wpk,
              const float* __restrict__ xproj,
              __half* __restrict__ h_out,
              float* __restrict__ c_out,
              float* __restrict__ outh,
              float* __restrict__ outc) {
    extern __shared__ __align__(16) unsigned char smc[];
    const uint32_t sb = (uint32_t)__cvta_generic_to_shared(smc);

    const int tid  = threadIdx.x;
    const int lane = tid & 31;
    const int w    = tid >> 5;
    const int nb   = blockIdx.x;   // 32 hcols
    const int mb   = blockIdx.y;   // 128 batch rows
    const int warp_m = (w >> 1) * 32;
    const int hsl    = (w & 1) * 16;

    float d[2][4][2][4];
    #pragma unroll
    for (int a = 0; a < 2; ++a)
        #pragma unroll
        for (int b = 0; b < 4; ++b)
            #pragma unroll
            for (int c = 0; c < 2; ++c)
                #pragma unroll
                for (int e = 0; e < 4; ++e) d[a][b][c][e] = 0.0f;

    const __half* Ag = h_in + (size_t)mb * 128 * 512;
    const __half* Bg = wpk + (size_t)nb * 128 * 512;

    // ---- cp.async stage issue: 1024 x 16B (A, B: 128 rows x 64B each) ----
    // per thread: 4 copies. idx -> arr(0..1), row(0..127), chunk(0..3)
    #define ISSUE(KC, SLOT) do {                                               \
        uint32_t sb0_ = sb + (SLOT) * STAGE_B;                                 \
        _Pragma("unroll")                                                      \
        for (int i_ = 0; i_ < 4; ++i_) {                                       \
            int idx_ = tid + i_ * 256;                                         \
            int arr_ = idx_ >> 9;                                              \
            int rc_  = idx_ & 511;                                             \
            int row_ = rc_ >> 2;                                               \
            int ch_  = rc_ & 3;                                                \
            const __half* s_ = (arr_ == 0 ? Ag : Bg)                           \
                               + (size_t)row_ * 512 + (KC) * 32 + ch_ * 8;     \
            uint32_t d_ = sb0_ + arr_ * ARR_B + row_ * 80 + ch_ * 16;          \
            cp16(d_, s_);                                                      \
        }                                                                      \
    } while (0)

    ISSUE(0, 0); cp_commit();
    ISSUE(1, 1); cp_commit();
    ISSUE(2, 2); cp_commit();

    const int arow  = warp_m + (lane & 15);
    const int acolo = (lane >> 4) * 8;
    const int brow  = hsl + ((lane >> 4) << 3) + (lane & 7);
    const int bcolo = ((lane >> 3) & 1) * 8;

    for (int kc = 0; kc < 16; ++kc) {
        cp_wait<2>();
        __syncthreads();
        if (kc + 3 < 16) { ISSUE(kc + 3, (kc + 3) & 3); }
        cp_commit();

        unsigned char* stg = smc + (kc & 3) * STAGE_B;
        __half (*Ah)[ROWPITCH] = (__half(*)[ROWPITCH])(stg);
        __half (*Bs)[ROWPITCH] = (__half(*)[ROWPITCH])(stg + ARR_B);

        #pragma unroll
        for (int kk = 0; kk < 32; kk += 16) {
            unsigned af[2][4];
            ldsm4(af[0], &Ah[arow][kk + acolo]);
            ldsm4(af[1], &Ah[arow + 16][kk + acolo]);

            #pragma unroll
            for (int g = 0; g < 4; ++g) {
                unsigned bf[4];
                ldsm4(bf, &Bs[g * 32 + brow][kk + bcolo]);
                #pragma unroll
                for (int mt = 0; mt < 2; ++mt) {
                    mma16816(d[mt][g][0], af[mt], bf[0], bf[1]);
                    mma16816(d[mt][g][1], af[mt], bf[2], bf[3]);
                }
            }
        }
    }
    #undef ISSUE

    // ---------- epilogue: thread-local gate fusion ----------
    const int gid = lane >> 2;
    const int tig = lane & 3;

    #pragma unroll
    for (int mt = 0; mt < 2; ++mt) {
        #pragma unroll
        for (int rh = 0; rh < 2; ++rh) {
            int m = mb * 128 + warp_m + mt * 16 + gid + rh * 8;
            #pragma unroll
            for (int j = 0; j < 2; ++j) {
                int hcol = nb * 32 + hsl + j * 8 + tig * 2;
                const float* xp = xproj + (size_t)m * GDIM + hcol;

                float2 gi = *(const float2*)(xp + 0 * 512);
                float2 gf = *(const float2*)(xp + 1 * 512);
                float2 gg = *(const float2*)(xp + 2 * 512);
                float2 go = *(const float2*)(xp + 3 * 512);

                gi.x += d[mt][0][j][rh * 2];  gi.y += d[mt][0][j][rh * 2 + 1];
                gf.x += d[mt][1][j][rh * 2];  gf.y += d[mt][1][j][rh * 2 + 1];
                gg.x += d[mt][2][j][rh * 2];  gg.y += d[mt][2][j][rh * 2 + 1];
                go.x += d[mt][3][j][rh * 2];  go.y += d[mt][3][j][rh * 2 + 1];

                float2 cv = *(const float2*)(c_in + (size_t)m * HDIM + hcol);

                float ix = sigf(gi.x), iy = sigf(gi.y);
                float fx = sigf(gf.x), fy = sigf(gf.y);
                float gx = tanhf_fast(gg.x), gy = tanhf_fast(gg.y);
                float ox = sigf(go.x), oy = sigf(go.y);

                float cnx = fx * cv.x + ix * gx;
                float cny = fy * cv.y + iy * gy;
                float hnx = ox * tanhf_fast(cnx);
                float hny = oy * tanhf_fast(cny);

                *(float2*)(c_out + (size_t)m * HDIM + hcol) = make_float2(cnx, cny);

                __half2 vh;
                vh.x = __float2half_rn(hnx);
                vh.y = __float2half_rn(hny);
                *(__half2*)(h_out + (size_t)m * HDIM + hcol) = vh;

                if (outh) {
                    *(float2*)(outh + (size_t)m * HDIM + hcol) = make_float2(hnx, hny);
                    if (outc)
                        *(float2*)(outc + (size_t)m * HDIM + hcol) = make_float2(cnx, cny);
                }
            }
        }
    }
}

// =====================================================================
extern "C" void kernel_launch(void* const* d_in, const int* in_sizes, int n_in,
                              void* d_out, int out_size) {
    const float* start_emb = (const float*)d_in[0];
    const float* h0        = (const float*)d_in[1];
    const float* c0        = (const float*)d_in[2];
    const float* w_ih      = (const float*)d_in[3];
    const float* w_hh      = (const float*)d_in[4];
    const float* b_ih      = (const float*)d_in[5];
    const float* b_hh      = (const float*)d_in[6];
    float* out = (float*)d_out;

    float *xproj, *cbuf;
    __half *hb, *wp;
    cudaGetSymbolAddress((void**)&xproj, g_xproj);
    cudaGetSymbolAddress((void**)&cbuf,  g_c);
    cudaGetSymbolAddress((void**)&hb,    g_h16);
    cudaGetSymbolAddress((void**)&wp,    g_wp);

    float* c[2]    = { cbuf, cbuf + NH };
    __half* h16[2] = { hb, hb + NH };

    cudaFuncSetAttribute(lstm_step_mma, cudaFuncAttributeMaxDynamicSharedMemorySize, SMEM_STEP);

    cudaMemcpyAsync(c[0], c0, (size_t)NH * sizeof(float), cudaMemcpyDeviceToDevice, 0);

    prep_w_kernel<<<(GDIM * 64) / 256, 256>>>(w_hh, wp);
    prep_h_kernel<<<(NH / 8) / 256, 256>>>(h0, h16[0]);

    dim3 grid_xp(HDIM / 32, BATCH / 64);
    xproj_kernel<<<grid_xp, XP_NT>>>(start_emb, w_ih, b_ih, b_hh, xproj);

    const bool out_has_c = (out_size >= 2 * NH);
    dim3 grid_step(16, 32);   // (hcol blocks of 32, batch blocks of 128)

    for (int t = 0; t < SEQL; ++t) {
        int cur = t & 1, nxt = (t + 1) & 1;
        float* outh = (t == SEQL - 1) ? out : nullptr;
        float* outc = (t == SEQL - 1 && out_has_c) ? (out + NH) : nullptr;
        lstm_step_mma<<<grid_step, 256, SMEM_STEP>>>(h16[cur], c[cur],
                                                     wp, xproj,
                                                     h16[nxt], c[nxt],
                                                     outh, outc);
    }
}

// round 7
// speedup vs baseline: 5.3777x; 1.1073x over previous
#include <cuda_runtime.h>
#include <cuda_fp16.h>
#include <cstdint>

// Problem constants (B=4096, E=512, H=512, SEQ=128)
#define BATCH 4096
#define EDIM  512
#define HDIM  512
#define GDIM  2048
#define SEQL  128
#define NH    (BATCH * HDIM)

// step-kernel pipeline config: K chunks of 64, 3 stages
#define KCHUNK   64
#define KITER    (HDIM / KCHUNK)       // 8
#define NSTAGE   3
#define ROWPITCH 72                    // halves per smem row (144B = 9x16B)
#define ARR_B    (128 * ROWPITCH * 2)  // 18432 B per array
#define STAGE_B  (2 * ARR_B)           // A + B = 36864 B
#define SMEM_STEP (NSTAGE * STAGE_B)   // 110592 B

// ---------------- device scratch (no allocation allowed) ----------------
__device__ __half g_xph[BATCH * GDIM];           // 16 MB, [m][hcol][gate] fp16
__device__ float g_c[2][NH];                     // 16 MB
__device__ __half g_h16[2][NH];                  // 8 MB
__device__ __half g_wp[GDIM * HDIM];             // 2 MB, packed [nb=16][p=128][k=512]

// ---------------- helpers ----------------
__device__ __forceinline__ float sigf(float x) {
    return __fdividef(1.0f, 1.0f + __expf(-x));
}
__device__ __forceinline__ float tanhf_fast(float x) {
    return 1.0f - __fdividef(2.0f, __expf(2.0f * x) + 1.0f);
}
__device__ __forceinline__ void ldsm4(unsigned r[4], const void* p) {
    unsigned a = (unsigned)__cvta_generic_to_shared(p);
    asm volatile("ldmatrix.sync.aligned.m8n8.x4.shared.b16 {%0,%1,%2,%3}, [%4];"
                 : "=r"(r[0]), "=r"(r[1]), "=r"(r[2]), "=r"(r[3]) : "r"(a));
}
__device__ __forceinline__ void mma16816(float d[4], const unsigned a[4],
                                         unsigned b0, unsigned b1) {
    asm volatile(
        "mma.sync.aligned.m16n8k16.row.col.f32.f16.f16.f32 "
        "{%0,%1,%2,%3}, {%4,%5,%6,%7}, {%8,%9}, {%0,%1,%2,%3};"
        : "+f"(d[0]), "+f"(d[1]), "+f"(d[2]), "+f"(d[3])
        : "r"(a[0]), "r"(a[1]), "r"(a[2]), "r"(a[3]), "r"(b0), "r"(b1));
}
__device__ __forceinline__ void cp16(uint32_t dst, const void* src) {
    asm volatile("cp.async.cg.shared.global [%0], [%1], 16;" :: "r"(dst), "l"(src) : "memory");
}
__device__ __forceinline__ void cp_commit() {
    asm volatile("cp.async.commit_group;" ::: "memory");
}
template <int N>
__device__ __forceinline__ void cp_wait() {
    asm volatile("cp.async.wait_group %0;" :: "n"(N) : "memory");
}

// ---------------- prep: W_hh -> packed fp16 ----------------
// layout: wp[nb][p][k], p = gate*32 + hc, nb = hcol block of 32
__global__ void prep_w_kernel(const float* __restrict__ w, __half* __restrict__ wp) {
    int t = blockIdx.x * blockDim.x + threadIdx.x;   // 2048 rows x 64 chunks
    int row = t >> 6;
    int k0  = (t & 63) * 8;
    int g = row >> 9, hcol = row & 511;
    int nb = hcol >> 5, hc = hcol & 31;
    int p = g * 32 + hc;
    const float* src = w + (size_t)row * 512 + k0;
    __half v[8];
    #pragma unroll
    for (int i = 0; i < 8; ++i) v[i] = __float2half_rn(src[i]);
    *(uint4*)(wp + (size_t)nb * 128 * 512 + (size_t)p * 512 + k0) = *(const uint4*)v;
}

// ---------------- prep: h0 -> fp16 ----------------
__global__ void prep_h_kernel(const float* __restrict__ h0, __half* __restrict__ h16) {
    int t = blockIdx.x * blockDim.x + threadIdx.x;   // NH/8 threads
    size_t base = (size_t)t * 8;
    __half v[8];
    #pragma unroll
    for (int i = 0; i < 8; ++i) v[i] = __float2half_rn(h0[base + i]);
    *(uint4*)(h16 + base) = *(const uint4*)v;
}

// =====================================================================
//  x-projection (one-time, fp32 SIMT) -> fp16 gate-interleaved output
// =====================================================================
#define XP_NT 256
__device__ __forceinline__ unsigned long long pack2(float x, float y) {
    unsigned long long r;
    asm("mov.b64 %0, {%1, %2};" : "=l"(r) : "f"(x), "f"(y));
    return r;
}
__device__ __forceinline__ void fma2(unsigned long long& acc, unsigned long long a, unsigned long long b) {
    asm("fma.rn.f32x2 %0, %1, %2, %0;" : "+l"(acc) : "l"(a), "l"(b));
}
__device__ __forceinline__ float2 unpack2(unsigned long long v) {
    float2 f;
    asm("mov.b64 {%0, %1}, %2;" : "=f"(f.x), "=f"(f.y) : "l"(v));
    return f;
}

__global__ void __launch_bounds__(XP_NT)
xproj_kernel(const float* __restrict__ x, const float* __restrict__ w_ih,
             const float* __restrict__ b_ih, const float* __restrict__ b_hh,
             __half* __restrict__ xph) {
    __shared__ float As[64][36];
    __shared__ float Bs[32][130];
    const int m0 = blockIdx.y * 64, n0 = blockIdx.x * 32;
    const int tid = threadIdx.x, ty = tid >> 4, tx = tid & 15;
    unsigned long long acc[4][4];
    #pragma unroll
    for (int r = 0; r < 4; ++r)
        #pragma unroll
        for (int g = 0; g < 4; ++g) acc[r][g] = 0ull;

    for (int kc = 0; kc < 512; kc += 32) {
        #pragma unroll
        for (int p = 0; p < 2; ++p) {
            int q = tid + p * XP_NT, m = q >> 3, kq = q & 7;
            *(float4*)(&As[m][kq * 4]) = *(const float4*)(x + (size_t)(m0 + m) * 512 + kc + kq * 4);
        }
        #pragma unroll
        for (int p = 0; p < 4; ++p) {
            int q = tid + p * XP_NT, n = q >> 3, kq = q & 7;
            int g = n >> 5, c = n & 31;
            float4 v = *(const float4*)(w_ih + (size_t)(g * 512 + n0 + c) * 512 + kc + kq * 4);
            Bs[kq * 4 + 0][n] = v.x; Bs[kq * 4 + 1][n] = v.y;
            Bs[kq * 4 + 2][n] = v.z; Bs[kq * 4 + 3][n] = v.w;
        }
        __syncthreads();
        #pragma unroll
        for (int k = 0; k < 32; ++k) {
            unsigned long long a2[4], b2[4];
            #pragma unroll
            for (int r = 0; r < 4; ++r) { float a = As[ty * 4 + r][k]; a2[r] = pack2(a, a); }
            #pragma unroll
            for (int g = 0; g < 4; ++g)
                b2[g] = *(const unsigned long long*)(&Bs[k][g * 32 + tx * 2]);
            #pragma unroll
            for (int r = 0; r < 4; ++r)
                #pragma unroll
                for (int g = 0; g < 4; ++g) fma2(acc[r][g], a2[r], b2[g]);
        }
        __syncthreads();
    }
    const int hcol = n0 + tx * 2;
    #pragma unroll
    for (int r = 0; r < 4; ++r) {
        int b = m0 + ty * 4 + r;
        __half* dst = xph + ((size_t)b * 512 + hcol) * 4;
        #pragma unroll
        for (int g = 0; g < 4; ++g) {
            int j = g * 512 + hcol;
            float2 v = unpack2(acc[r][g]);
            v.x += b_ih[j] + b_hh[j];
            v.y += b_ih[j + 1] + b_hh[j + 1];
            dst[g]     = __float2half_rn(v.x);
            dst[4 + g] = __float2half_rn(v.y);
        }
    }
}

// =====================================================================
//  LSTM step: fp16 HMMA GEMM, K-chunk=64, 3-stage cp.async pipeline
//  Block: 128 batch rows x 32 hcols x 4 gates; 8 warps (32m x 16hc);
//  2 CTAs/SM; 8 barriers per kernel.
// =====================================================================
__global__ void __launch_bounds__(256, 2)
lstm_step_mma(const __half* __restrict__ h_in,
              const float* __restrict__ c_in,
              const __half* __restrict__ wpk,
              const __half* __restrict__ xph,
              __half* __restrict__ h_out,
              float* __restrict__ c_out,
              float* __restrict__ outh,
              float* __restrict__ outc) {
    extern __shared__ __align__(16) unsigned char smc[];
    const uint32_t sb = (uint32_t)__cvta_generic_to_shared(smc);

    const int tid  = threadIdx.x;
    const int lane = tid & 31;
    const int w    = tid >> 5;
    const int nb   = blockIdx.x;   // 32 hcols
    const int mb   = blockIdx.y;   // 128 batch rows
    const int warp_m = (w >> 1) * 32;
    const int hsl    = (w & 1) * 16;

    float d[2][4][2][4];
    #pragma unroll
    for (int a = 0; a < 2; ++a)
        #pragma unroll
        for (int b = 0; b < 4; ++b)
            #pragma unroll
            for (int c = 0; c < 2; ++c)
                #pragma unroll
                for (int e = 0; e < 4; ++e) d[a][b][c][e] = 0.0f;

    const __half* Ag = h_in + (size_t)mb * 128 * 512;
    const __half* Bg = wpk + (size_t)nb * 128 * 512;

    // ---- cp.async stage issue: 2048 x 16B (A, B: 128 rows x 128B each) ----
    // per thread: 8 copies. idx -> arr(0..1), row(0..127), chunk(0..7)
    #define ISSUE(KC, SLOT) do {                                               \
        uint32_t sb0_ = sb + (SLOT) * STAGE_B;                                 \
        _Pragma("unroll")                                                      \
        for (int i_ = 0; i_ < 8; ++i_) {                                       \
            int idx_ = tid + i_ * 256;                                         \
            int arr_ = idx_ >> 10;                                             \
            int rc_  = idx_ & 1023;                                            \
            int row_ = rc_ >> 3;                                               \
            int ch_  = rc_ & 7;                                                \
            const __half* s_ = (arr_ == 0 ? Ag : Bg)                           \
                               + (size_t)row_ * 512 + (KC) * KCHUNK + ch_ * 8; \
            uint32_t d_ = sb0_ + arr_ * ARR_B + row_ * (ROWPITCH * 2) + ch_ * 16; \
            cp16(d_, s_);                                                      \
        }                                                                      \
    } while (0)

    ISSUE(0, 0); cp_commit();
    ISSUE(1, 1); cp_commit();

    const int arow  = warp_m + (lane & 15);
    const int acolo = (lane >> 4) * 8;
    const int brow  = hsl + ((lane >> 4) << 3) + (lane & 7);
    const int bcolo = ((lane >> 3) & 1) * 8;

    for (int kc = 0; kc < KITER; ++kc) {
        cp_wait<1>();
        __syncthreads();
        if (kc + 2 < KITER) { ISSUE(kc + 2, (kc + 2) % NSTAGE); }
        cp_commit();

        unsigned char* stg = smc + (kc % NSTAGE) * STAGE_B;
        __half (*Ah)[ROWPITCH] = (__half(*)[ROWPITCH])(stg);
        __half (*Bs)[ROWPITCH] = (__half(*)[ROWPITCH])(stg + ARR_B);

        #pragma unroll
        for (int kk = 0; kk < KCHUNK; kk += 16) {
            unsigned af[2][4];
            ldsm4(af[0], &Ah[arow][kk + acolo]);
            ldsm4(af[1], &Ah[arow + 16][kk + acolo]);

            #pragma unroll
            for (int g = 0; g < 4; ++g) {
                unsigned bf[4];
                ldsm4(bf, &Bs[g * 32 + brow][kk + bcolo]);
                #pragma unroll
                for (int mt = 0; mt < 2; ++mt) {
                    mma16816(d[mt][g][0], af[mt], bf[0], bf[1]);
                    mma16816(d[mt][g][1], af[mt], bf[2], bf[3]);
                }
            }
        }
    }
    #undef ISSUE

    // ---------- epilogue: thread-local gate fusion ----------
    const int gid = lane >> 2;
    const int tig = lane & 3;

    #pragma unroll
    for (int mt = 0; mt < 2; ++mt) {
        #pragma unroll
        for (int rh = 0; rh < 2; ++rh) {
            int m = mb * 128 + warp_m + mt * 16 + gid + rh * 8;
            #pragma unroll
            for (int j = 0; j < 2; ++j) {
                int hcol = nb * 32 + hsl + j * 8 + tig * 2;

                // one 16B load: [hcol: i,f,g,o | hcol+1: i,f,g,o] fp16
                uint4 pk = *(const uint4*)(xph + ((size_t)m * 512 + hcol) * 4);
                __half2* hp = (__half2*)&pk;
                float2 if0 = __half22float2(hp[0]);
                float2 go0 = __half22float2(hp[1]);
                float2 if1 = __half22float2(hp[2]);
                float2 go1 = __half22float2(hp[3]);

                float gix = if0.x + d[mt][0][j][rh * 2];
                float giy = if1.x + d[mt][0][j][rh * 2 + 1];
                float gfx = if0.y + d[mt][1][j][rh * 2];
                float gfy = if1.y + d[mt][1][j][rh * 2 + 1];
                float ggx = go0.x + d[mt][2][j][rh * 2];
                float ggy = go1.x + d[mt][2][j][rh * 2 + 1];
                float gox = go0.y + d[mt][3][j][rh * 2];
                float goy = go1.y + d[mt][3][j][rh * 2 + 1];

                float2 cv = *(const float2*)(c_in + (size_t)m * HDIM + hcol);

                float ix = sigf(gix), iy = sigf(giy);
                float fx = sigf(gfx), fy = sigf(gfy);
                float gx = tanhf_fast(ggx), gy = tanhf_fast(ggy);
                float ox = sigf(gox), oy = sigf(goy);

                float cnx = fx * cv.x + ix * gx;
                float cny = fy * cv.y + iy * gy;
                float hnx = ox * tanhf_fast(cnx);
                float hny = oy * tanhf_fast(cny);

                *(float2*)(c_out + (size_t)m * HDIM + hcol) = make_float2(cnx, cny);

                __half2 vh;
                vh.x = __float2half_rn(hnx);
                vh.y = __float2half_rn(hny);
                *(__half2*)(h_out + (size_t)m * HDIM + hcol) = vh;

                if (outh) {
                    *(float2*)(outh + (size_t)m * HDIM + hcol) = make_float2(hnx, hny);
                    if (outc)
                        *(float2*)(outc + (size_t)m * HDIM + hcol) = make_float2(cnx, cny);
                }
            }
        }
    }
}

// =====================================================================
extern "C" void kernel_launch(void* const* d_in, const int* in_sizes, int n_in,
                              void* d_out, int out_size) {
    const float* start_emb = (const float*)d_in[0];
    const float* h0        = (const float*)d_in[1];
    const float* c0        = (const float*)d_in[2];
    const float* w_ih      = (const float*)d_in[3];
    const float* w_hh      = (const float*)d_in[4];
    const float* b_ih      = (const float*)d_in[5];
    const float* b_hh      = (const float*)d_in[6];
    float* out = (float*)d_out;

    float* cbuf;
    __half *xph, *hb, *wp;
    cudaGetSymbolAddress((void**)&xph,  g_xph);
    cudaGetSymbolAddress((void**)&cbuf, g_c);
    cudaGetSymbolAddress((void**)&hb,   g_h16);
    cudaGetSymbolAddress((void**)&wp,   g_wp);

    float* c[2]    = { cbuf, cbuf + NH };
    __half* h16[2] = { hb, hb + NH };

    cudaFuncSetAttribute(lstm_step_mma, cudaFuncAttributeMaxDynamicSharedMemorySize, SMEM_STEP);

    cudaMemcpyAsync(c[0], c0, (size_t)NH * sizeof(float), cudaMemcpyDeviceToDevice, 0);

    prep_w_kernel<<<(GDIM * 64) / 256, 256>>>(w_hh, wp);
    prep_h_kernel<<<(NH / 8) / 256, 256>>>(h0, h16[0]);

    dim3 grid_xp(HDIM / 32, BATCH / 64);
    xproj_kernel<<<grid_xp, XP_NT>>>(start_emb, w_ih, b_ih, b_hh, xph);

    const bool out_has_c = (out_size >= 2 * NH);
    dim3 grid_step(16, 32);   // (hcol blocks of 32, batch blocks of 128)

    for (int t = 0; t < SEQL; ++t) {
        int cur = t & 1, nxt = (t + 1) & 1;
        float* outh = (t == SEQL - 1) ? out : nullptr;
        float* outc = (t == SEQL - 1 && out_has_c) ? (out + NH) : nullptr;
        lstm_step_mma<<<grid_step, 256, SMEM_STEP>>>(h16[cur], c[cur],
                                                     wp, xph,
                                                     h16[nxt], c[nxt],
                                                     outh, outc);
    }
}

// round 8
// speedup vs baseline: 6.5683x; 1.2214x over previous
#include <cuda_runtime.h>
#include <cuda_fp16.h>
#include <cstdint>

// Problem constants (B=4096, E=512, H=512, SEQ=128)
#define BATCH 4096
#define EDIM  512
#define HDIM  512
#define GDIM  2048
#define SEQL  128
#define NH    (BATCH * HDIM)

// step pipeline config: K chunks of 64, 3 stages
#define KCHUNK   64
#define KITER    (HDIM / KCHUNK)       // 8
#define NSTAGE   3
#define ROWPITCH 72                    // halves per smem row (144B = 9x16B)
#define ARR_B    (128 * ROWPITCH * 2)  // 18432 B per array
#define STAGE_B  (2 * ARR_B)           // A + B = 36864 B
#define SMEM_STEP (NSTAGE * STAGE_B)   // 110592 B

// ---------------- device scratch (no allocation allowed) ----------------
__device__ __half g_xph[BATCH * GDIM];           // 16 MB, [m][hcol][gate] fp16
__device__ float g_c[2][NH];                     // 16 MB
__device__ __half g_h16[2][NH];                  // 8 MB
__device__ __half g_wp[GDIM * HDIM];             // 2 MB, packed [nb=16][p=128][k=512]
__device__ unsigned g_cnt[32];                   // per-mb step completion counters

// ---------------- helpers ----------------
__device__ __forceinline__ float sigf(float x) {
    return __fdividef(1.0f, 1.0f + __expf(-x));
}
__device__ __forceinline__ float tanhf_fast(float x) {
    return 1.0f - __fdividef(2.0f, __expf(2.0f * x) + 1.0f);
}
__device__ __forceinline__ void ldsm4(unsigned r[4], const void* p) {
    unsigned a = (unsigned)__cvta_generic_to_shared(p);
    asm volatile("ldmatrix.sync.aligned.m8n8.x4.shared.b16 {%0,%1,%2,%3}, [%4];"
                 : "=r"(r[0]), "=r"(r[1]), "=r"(r[2]), "=r"(r[3]) : "r"(a));
}
__device__ __forceinline__ void mma16816(float d[4], const unsigned a[4],
                                         unsigned b0, unsigned b1) {
    asm volatile(
        "mma.sync.aligned.m16n8k16.row.col.f32.f16.f16.f32 "
        "{%0,%1,%2,%3}, {%4,%5,%6,%7}, {%8,%9}, {%0,%1,%2,%3};"
        : "+f"(d[0]), "+f"(d[1]), "+f"(d[2]), "+f"(d[3])
        : "r"(a[0]), "r"(a[1]), "r"(a[2]), "r"(a[3]), "r"(b0), "r"(b1));
}
__device__ __forceinline__ void cp16(uint32_t dst, const void* src) {
    asm volatile("cp.async.cg.shared.global [%0], [%1], 16;" :: "r"(dst), "l"(src) : "memory");
}
__device__ __forceinline__ void cp_commit() {
    asm volatile("cp.async.commit_group;" ::: "memory");
}
template <int N>
__device__ __forceinline__ void cp_wait() {
    asm volatile("cp.async.wait_group %0;" :: "n"(N) : "memory");
}

// ---------------- prep: W_hh -> packed fp16 ----------------
// layout: wp[nb][p][k], p = gate*32 + hc, nb = hcol block of 32
__global__ void prep_w_kernel(const float* __restrict__ w, __half* __restrict__ wp) {
    int t = blockIdx.x * blockDim.x + threadIdx.x;   // 2048 rows x 64 chunks
    int row = t >> 6;
    int k0  = (t & 63) * 8;
    int g = row >> 9, hcol = row & 511;
    int nb = hcol >> 5, hc = hcol & 31;
    int p = g * 32 + hc;
    const float* src = w + (size_t)row * 512 + k0;
    __half v[8];
    #pragma unroll
    for (int i = 0; i < 8; ++i) v[i] = __float2half_rn(src[i]);
    *(uint4*)(wp + (size_t)nb * 128 * 512 + (size_t)p * 512 + k0) = *(const uint4*)v;
}

// ---------------- prep: h0 -> fp16 ----------------
__global__ void prep_h_kernel(const float* __restrict__ h0, __half* __restrict__ h16) {
    int t = blockIdx.x * blockDim.x + threadIdx.x;   // NH/8 threads
    size_t base = (size_t)t * 8;
    __half v[8];
    #pragma unroll
    for (int i = 0; i < 8; ++i) v[i] = __float2half_rn(h0[base + i]);
    *(uint4*)(h16 + base) = *(const uint4*)v;
}

// =====================================================================
//  x-projection (one-time, fp32 SIMT) -> fp16 gate-interleaved output
// =====================================================================
#define XP_NT 256
__device__ __forceinline__ unsigned long long pack2(float x, float y) {
    unsigned long long r;
    asm("mov.b64 %0, {%1, %2};" : "=l"(r) : "f"(x), "f"(y));
    return r;
}
__device__ __forceinline__ void fma2(unsigned long long& acc, unsigned long long a, unsigned long long b) {
    asm("fma.rn.f32x2 %0, %1, %2, %0;" : "+l"(acc) : "l"(a), "l"(b));
}
__device__ __forceinline__ float2 unpack2(unsigned long long v) {
    float2 f;
    asm("mov.b64 {%0, %1}, %2;" : "=f"(f.x), "=f"(f.y) : "l"(v));
    return f;
}

__global__ void __launch_bounds__(XP_NT)
xproj_kernel(const float* __restrict__ x, const float* __restrict__ w_ih,
             const float* __restrict__ b_ih, const float* __restrict__ b_hh,
             __half* __restrict__ xph) {
    __shared__ float As[64][36];
    __shared__ float Bs[32][130];
    const int m0 = blockIdx.y * 64, n0 = blockIdx.x * 32;
    const int tid = threadIdx.x, ty = tid >> 4, tx = tid & 15;
    unsigned long long acc[4][4];
    #pragma unroll
    for (int r = 0; r < 4; ++r)
        #pragma unroll
        for (int g = 0; g < 4; ++g) acc[r][g] = 0ull;

    for (int kc = 0; kc < 512; kc += 32) {
        #pragma unroll
        for (int p = 0; p < 2; ++p) {
            int q = tid + p * XP_NT, m = q >> 3, kq = q & 7;
            *(float4*)(&As[m][kq * 4]) = *(const float4*)(x + (size_t)(m0 + m) * 512 + kc + kq * 4);
        }
        #pragma unroll
        for (int p = 0; p < 4; ++p) {
            int q = tid + p * XP_NT, n = q >> 3, kq = q & 7;
            int g = n >> 5, c = n & 31;
            float4 v = *(const float4*)(w_ih + (size_t)(g * 512 + n0 + c) * 512 + kc + kq * 4);
            Bs[kq * 4 + 0][n] = v.x; Bs[kq * 4 + 1][n] = v.y;
            Bs[kq * 4 + 2][n] = v.z; Bs[kq * 4 + 3][n] = v.w;
        }
        __syncthreads();
        #pragma unroll
        for (int k = 0; k < 32; ++k) {
            unsigned long long a2[4], b2[4];
            #pragma unroll
            for (int r = 0; r < 4; ++r) { float a = As[ty * 4 + r][k]; a2[r] = pack2(a, a); }
            #pragma unroll
            for (int g = 0; g < 4; ++g)
                b2[g] = *(const unsigned long long*)(&Bs[k][g * 32 + tx * 2]);
            #pragma unroll
            for (int r = 0; r < 4; ++r)
                #pragma unroll
                for (int g = 0; g < 4; ++g) fma2(acc[r][g], a2[r], b2[g]);
        }
        __syncthreads();
    }
    const int hcol = n0 + tx * 2;
    #pragma unroll
    for (int r = 0; r < 4; ++r) {
        int b = m0 + ty * 4 + r;
        __half* dst = xph + ((size_t)b * 512 + hcol) * 4;
        #pragma unroll
        for (int g = 0; g < 4; ++g) {
            int j = g * 512 + hcol;
            float2 v = unpack2(acc[r][g]);
            v.x += b_ih[j] + b_hh[j];
            v.y += b_ih[j + 1] + b_hh[j + 1];
            dst[g]     = __float2half_rn(v.x);
            dst[4 + g] = __float2half_rn(v.y);
        }
    }
}

// =====================================================================
//  Persistent LSTM: one CTA per (step, mb, nb) tile.
//  grid = (512, 128): blockIdx.x = mb*16 + nb, blockIdx.y = step.
//  Cross-step dependency via per-mb counters (decoupled lookback).
// =====================================================================
__global__ void __launch_bounds__(256, 2)
lstm_mega(const __half* __restrict__ wpk,
          const __half* __restrict__ xph,
          __half* __restrict__ hbase,
          float* __restrict__ cbase,
          float* __restrict__ outh,
          float* __restrict__ outc,
          unsigned* __restrict__ cnt) {
    extern __shared__ __align__(16) unsigned char smc[];
    const uint32_t sb = (uint32_t)__cvta_generic_to_shared(smc);

    const int t    = blockIdx.y;
    const int nb   = blockIdx.x & 15;   // 32 hcols
    const int mb   = blockIdx.x >> 4;   // 128 batch rows
    const int tid  = threadIdx.x;
    const int lane = tid & 31;
    const int w    = tid >> 5;
    const int warp_m = (w >> 1) * 32;
    const int hsl    = (w & 1) * 16;

    const __half* h_in  = hbase + (size_t)(t & 1) * NH;
    __half*       h_out = hbase + (size_t)((t + 1) & 1) * NH;
    const float*  c_in  = cbase + (size_t)(t & 1) * NH;
    float*        c_out = cbase + (size_t)((t + 1) & 1) * NH;

    // ---- wait for step t-1 producers of this mb (all 16 nb slices) ----
    if (t > 0) {
        if (tid == 0) {
            const unsigned target = 16u * (unsigned)t;
            volatile unsigned* p = cnt + mb;
            while (*p < target) __nanosleep(64);
            __threadfence();
        }
        __syncthreads();
    }

    float d[2][4][2][4];
    #pragma unroll
    for (int a = 0; a < 2; ++a)
        #pragma unroll
        for (int b = 0; b < 4; ++b)
            #pragma unroll
            for (int c = 0; c < 2; ++c)
                #pragma unroll
                for (int e = 0; e < 4; ++e) d[a][b][c][e] = 0.0f;

    const __half* Ag = h_in + (size_t)mb * 128 * 512;
    const __half* Bg = wpk + (size_t)nb * 128 * 512;

    // ---- cp.async stage issue: 2048 x 16B (A, B: 128 rows x 128B each) ----
    #define ISSUE(KC, SLOT) do {                                               \
        uint32_t sb0_ = sb + (SLOT) * STAGE_B;                                 \
        _Pragma("unroll")                                                      \
        for (int i_ = 0; i_ < 8; ++i_) {                                       \
            int idx_ = tid + i_ * 256;                                         \
            int arr_ = idx_ >> 10;                                             \
            int rc_  = idx_ & 1023;                                            \
            int row_ = rc_ >> 3;                                               \
            int ch_  = rc_ & 7;                                                \
            const __half* s_ = (arr_ == 0 ? Ag : Bg)                           \
                               + (size_t)row_ * 512 + (KC) * KCHUNK + ch_ * 8; \
            uint32_t d_ = sb0_ + arr_ * ARR_B + row_ * (ROWPITCH * 2) + ch_ * 16; \
            cp16(d_, s_);                                                      \
        }                                                                      \
    } while (0)

    ISSUE(0, 0); cp_commit();
    ISSUE(1, 1); cp_commit();

    const int arow  = warp_m + (lane & 15);
    const int acolo = (lane >> 4) * 8;
    const int brow  = hsl + ((lane >> 4) << 3) + (lane & 7);
    const int bcolo = ((lane >> 3) & 1) * 8;

    for (int kc = 0; kc < KITER; ++kc) {
        cp_wait<1>();
        __syncthreads();
        if (kc + 2 < KITER) { ISSUE(kc + 2, (kc + 2) % NSTAGE); }
        cp_commit();

        unsigned char* stg = smc + (kc % NSTAGE) * STAGE_B;
        __half (*Ah)[ROWPITCH] = (__half(*)[ROWPITCH])(stg);
        __half (*Bs)[ROWPITCH] = (__half(*)[ROWPITCH])(stg + ARR_B);

        #pragma unroll
        for (int kk = 0; kk < KCHUNK; kk += 16) {
            unsigned af[2][4];
            ldsm4(af[0], &Ah[arow][kk + acolo]);
            ldsm4(af[1], &Ah[arow + 16][kk + acolo]);

            #pragma unroll
            for (int g = 0; g < 4; ++g) {
                unsigned bf[4];
                ldsm4(bf, &Bs[g * 32 + brow][kk + bcolo]);
                #pragma unroll
                for (int mt = 0; mt < 2; ++mt) {
                    mma16816(d[mt][g][0], af[mt], bf[0], bf[1]);
                    mma16816(d[mt][g][1], af[mt], bf[2], bf[3]);
                }
            }
        }
    }
    #undef ISSUE

    // ---------- epilogue: thread-local gate fusion ----------
    const int gid = lane >> 2;
    const int tig = lane & 3;
    const bool last = (t == SEQL - 1);

    #pragma unroll
    for (int mt = 0; mt < 2; ++mt) {
        #pragma unroll
        for (int rh = 0; rh < 2; ++rh) {
            int m = mb * 128 + warp_m + mt * 16 + gid + rh * 8;
            #pragma unroll
            for (int j = 0; j < 2; ++j) {
                int hcol = nb * 32 + hsl + j * 8 + tig * 2;

                // one 16B load: [hcol: i,f,g,o | hcol+1: i,f,g,o] fp16
                uint4 pk = *(const uint4*)(xph + ((size_t)m * 512 + hcol) * 4);
                __half2* hp = (__half2*)&pk;
                float2 if0 = __half22float2(hp[0]);
                float2 go0 = __half22float2(hp[1]);
                float2 if1 = __half22float2(hp[2]);
                float2 go1 = __half22float2(hp[3]);

                float gix = if0.x + d[mt][0][j][rh * 2];
                float giy = if1.x + d[mt][0][j][rh * 2 + 1];
                float gfx = if0.y + d[mt][1][j][rh * 2];
                float gfy = if1.y + d[mt][1][j][rh * 2 + 1];
                float ggx = go0.x + d[mt][2][j][rh * 2];
                float ggy = go1.x + d[mt][2][j][rh * 2 + 1];
                float gox = go0.y + d[mt][3][j][rh * 2];
                float goy = go1.y + d[mt][3][j][rh * 2 + 1];

                float2 cv = *(const float2*)(c_in + (size_t)m * HDIM + hcol);

                float ix = sigf(gix), iy = sigf(giy);
                float fx = sigf(gfx), fy = sigf(gfy);
                float gx = tanhf_fast(ggx), gy = tanhf_fast(ggy);
                float ox = sigf(gox), oy = sigf(goy);

                float cnx = fx * cv.x + ix * gx;
                float cny = fy * cv.y + iy * gy;
                float hnx = ox * tanhf_fast(cnx);
                float hny = oy * tanhf_fast(cny);

                *(float2*)(c_out + (size_t)m * HDIM + hcol) = make_float2(cnx, cny);

                __half2 vh;
                vh.x = __float2half_rn(hnx);
                vh.y = __float2half_rn(hny);
                *(__half2*)(h_out + (size_t)m * HDIM + hcol) = vh;

                if (last) {
                    *(float2*)(outh + (size_t)m * HDIM + hcol) = make_float2(hnx, hny);
                    if (outc)
                        *(float2*)(outc + (size_t)m * HDIM + hcol) = make_float2(cnx, cny);
                }
            }
        }
    }

    // ---- signal: this (t, mb, nb) slice complete ----
    __threadfence();
    __syncthreads();
    if (tid == 0) atomicAdd(cnt + mb, 1u);
}

// =====================================================================
extern "C" void kernel_launch(void* const* d_in, const int* in_sizes, int n_in,
                              void* d_out, int out_size) {
    const float* start_emb = (const float*)d_in[0];
    const float* h0        = (const float*)d_in[1];
    const float* c0        = (const float*)d_in[2];
    const float* w_ih      = (const float*)d_in[3];
    const float* w_hh      = (const float*)d_in[4];
    const float* b_ih      = (const float*)d_in[5];
    const float* b_hh      = (const float*)d_in[6];
    float* out = (float*)d_out;

    float* cbuf;
    __half *xph, *hb, *wp;
    unsigned* cnt;
    cudaGetSymbolAddress((void**)&xph,  g_xph);
    cudaGetSymbolAddress((void**)&cbuf, g_c);
    cudaGetSymbolAddress((void**)&hb,   g_h16);
    cudaGetSymbolAddress((void**)&wp,   g_wp);
    cudaGetSymbolAddress((void**)&cnt,  g_cnt);

    cudaFuncSetAttribute(lstm_mega, cudaFuncAttributeMaxDynamicSharedMemorySize, SMEM_STEP);

    cudaMemsetAsync(cnt, 0, 32 * sizeof(unsigned), 0);
    cudaMemcpyAsync(cbuf, c0, (size_t)NH * sizeof(float), cudaMemcpyDeviceToDevice, 0);

    prep_w_kernel<<<(GDIM * 64) / 256, 256>>>(w_hh, wp);
    prep_h_kernel<<<(NH / 8) / 256, 256>>>(h0, hb);

    dim3 grid_xp(HDIM / 32, BATCH / 64);
    xproj_kernel<<<grid_xp, XP_NT>>>(start_emb, w_ih, b_ih, b_hh, xph);

    const bool out_has_c = (out_size >= 2 * NH);
    float* outc = out_has_c ? (out + NH) : nullptr;

    dim3 grid_mega(512, SEQL);   // (tile: mb*16+nb, step)
    lstm_mega<<<grid_mega, 256, SMEM_STEP>>>(wp, xph, hb, cbuf, out, outc, cnt);
}